// round 10
// baseline (speedup 1.0000x reference)
#include <cuda_runtime.h>
#include <cuda_bf16.h>
#include <math.h>

// Problem constants
#define VOCAB 50000
#define D_EMB 256
#define H_DIM 512
#define B_SZ  64
#define T_LEN 512
#define KTOT  (D_EMB + H_DIM)   // 768
#define G4H   (4 * H_DIM)       // 2048

// Persistent-kernel config
#define NCTA    128             // each CTA owns H_DIM/NCTA = 4 h-columns -> 16 gate cols
#define NTHR    256             // 8 warps; warp w = k-group w
#define HC      4               // h cols per CTA
#define KPW     (KTOT / 8)      // 96 k's per warp

// SMEM layout (floats): Ws[768*16] then red[8 warps][32 lanes][34 floats]
#define WS_FLOATS   (KTOT * 16)                 // 12288
#define RED_STRIDE  34                           // 32 floats payload + 2 pad (keeps 8B align, spreads banks)
#define RED_FLOATS  (8 * 32 * RED_STRIDE)        // 8704
#define SMEM_FLOATS (WS_FLOATS + RED_FLOATS)     // 20992
#define SMEM_BYTES  (SMEM_FLOATS * 4)            // 83968

typedef unsigned long long u64;

// -------- device scratch (allocation-free rule: __device__ globals) --------
__device__ float    g_XT[T_LEN * D_EMB * B_SZ];      // transposed embedded input  [t][d][b]
__device__ float    g_hbuf[2][H_DIM * B_SZ];         // transposed h double buffer [h][b]
__device__ unsigned g_bar_count = 0;
__device__ unsigned g_bar_gen   = 0;

// -------- packed f32x2 helpers (FFMA2: 2x fp32 FMA rate on sm_103a) --------
__device__ __forceinline__ u64 pack2(float lo, float hi) {
    u64 r; asm("mov.b64 %0, {%1, %2};" : "=l"(r) : "f"(lo), "f"(hi)); return r;
}
__device__ __forceinline__ u64 bcast2(float v) {
    u64 r; asm("mov.b64 %0, {%1, %1};" : "=l"(r) : "f"(v)); return r;
}
__device__ __forceinline__ u64 fma2(u64 a, u64 b, u64 c) {
    u64 d; asm("fma.rn.f32x2 %0, %1, %2, %3;" : "=l"(d) : "l"(a), "l"(b), "l"(c)); return d;
}

__device__ __forceinline__ float sigf(float x) {
    return 1.0f / (1.0f + __expf(-x));
}

// -------- grid-wide sense-reversing barrier (128 co-resident CTAs) --------
__device__ __forceinline__ void grid_sync() {
    __syncthreads();
    if (threadIdx.x == 0) {
        __threadfence();                                   // publish our h writes (also CCTL.IVALL)
        unsigned gen = *(volatile unsigned*)&g_bar_gen;    // read BEFORE arriving: race-free
        unsigned tkt = atomicAdd(&g_bar_count, 1u);
        if (tkt == NCTA - 1) {
            atomicExch(&g_bar_count, 0u);
            __threadfence();
            atomicAdd(&g_bar_gen, 1u);                     // release
        } else {
            while (*(volatile unsigned*)&g_bar_gen == gen) { __nanosleep(64); }
        }
        __threadfence();                                   // invalidate L1 before reading peers' h
    }
    __syncthreads();
}

// ============================================================================
// Kernel 1: embedding gather + transpose to XT[t][d][b]; also zero h_buf[0].
// grid = T_LEN blocks, 256 threads. Thread (b = tid&63, q = tid>>6) copies
// 64 d's of embedding row word_indices[b][t] into column b of XT.
// ============================================================================
__global__ void gather_transpose_kernel(const int* __restrict__ wi,
                                        const float* __restrict__ emb) {
    int t   = blockIdx.x;
    int tid = threadIdx.x;
    int b   = tid & 63;
    int q   = tid >> 6;                 // 0..3 (which 64-d quarter)

    int row = wi[b * T_LEN + t];
    const float* er = emb + (size_t)row * D_EMB + q * 64;
    float* xo = g_XT + (size_t)t * D_EMB * B_SZ;   // [d][b]

#pragma unroll
    for (int i = 0; i < 64; i += 4) {
        float4 v = __ldg((const float4*)(er + i));
        int d = q * 64 + i;
        xo[(d + 0) * B_SZ + b] = v.x;
        xo[(d + 1) * B_SZ + b] = v.y;
        xo[(d + 2) * B_SZ + b] = v.z;
        xo[(d + 3) * B_SZ + b] = v.w;
    }

    // zero h0 (block t owns h-row t); must be redone EVERY launch since the
    // last LSTM step writes buffer 0.
    if (tid < B_SZ) g_hbuf[0][t * B_SZ + tid] = 0.0f;
}

// ============================================================================
// Kernel 2: persistent LSTM. 128 CTAs x 256 threads, all steps in one launch.
//   - W slice [768 x 16] lives in SMEM for the whole kernel
//   - warp w computes k in [w*96, (w+1)*96) for the full 64x16 output tile
//     (batch paired into f32x2); partials reduced through SMEM
//   - epilogue thread (b = tid&63, cl = tid>>6) owns state (c,h) in registers
// ============================================================================
__global__ void __launch_bounds__(NTHR, 1)
lstm_persistent_kernel(const float* __restrict__ kern,
                       const float* __restrict__ bias,
                       const int*   __restrict__ num_words,
                       float*       __restrict__ out) {
    extern __shared__ float smem[];
    float* Ws  = smem;               // [k][16 cols], col = gate*4 + cl
    float* red = smem + WS_FLOATS;   // [w][lane][RED_STRIDE]

    const int tid  = threadIdx.x;
    const int w    = tid >> 5;
    const int lane = tid & 31;
    const int bg   = lane >> 2;      // batch group 0..7  (rows bg*8 .. bg*8+7)
    const int cg   = lane & 3;       // gate index 0..3   (cols cg*4 .. cg*4+3)
    const int hc0  = blockIdx.x * HC;

    // ---- load weight slice into SMEM (once) ----
    for (int idx = tid; idx < WS_FLOATS; idx += NTHR) {
        int k  = idx >> 4;
        int c  = idx & 15;
        int g  = c >> 2;
        int cl = c & 3;
        Ws[idx] = kern[(size_t)k * G4H + g * H_DIM + hc0 + cl];
    }

    // ---- epilogue-role per-thread state ----
    const int b  = tid & 63;
    const int cl = tid >> 6;         // 0..3 local h col
    float c_reg = 0.0f, h_reg = 0.0f;
    const int nw_b = num_words[b];
    float biasr[4];
#pragma unroll
    for (int g = 0; g < 4; ++g) biasr[g] = bias[g * H_DIM + hc0 + cl];

    __syncthreads();

    const int k0  = w * KPW;
    const int k1  = k0 + KPW;
    const int kxe = (k1 < D_EMB) ? k1 : D_EMB;   // x-part end
    const int khs = (k0 > D_EMB) ? k0 : D_EMB;   // h-part start
    float* slot = red + (w * 32 + lane) * RED_STRIDE;

    for (int t = 0; t < T_LEN; ++t) {
        if (t > 0) grid_sync();

        const int p = t & 1;
        const float* xbase = g_XT + (size_t)t * D_EMB * B_SZ;
        const float* hbase = g_hbuf[p] - D_EMB * B_SZ;   // index with k in [256,768)

        u64 acc[4][4];
#pragma unroll
        for (int i = 0; i < 4; ++i)
#pragma unroll
            for (int j = 0; j < 4; ++j) acc[i][j] = 0ull;

#define KBODY(BASE, K)                                                         \
        {                                                                      \
            const float4* rp = (const float4*)((BASE) + (K) * B_SZ + bg * 8);  \
            float4 v0 = __ldcg(rp);                                            \
            float4 v1 = __ldcg(rp + 1);                                        \
            float4 wv = *(const float4*)(Ws + (K) * 16 + cg * 4);              \
            u64 a0 = pack2(v0.x, v0.y), a1 = pack2(v0.z, v0.w);                \
            u64 a2 = pack2(v1.x, v1.y), a3 = pack2(v1.z, v1.w);                \
            u64 w0 = bcast2(wv.x), w1 = bcast2(wv.y);                          \
            u64 w2 = bcast2(wv.z), w3 = bcast2(wv.w);                          \
            acc[0][0] = fma2(a0, w0, acc[0][0]);                               \
            acc[0][1] = fma2(a0, w1, acc[0][1]);                               \
            acc[0][2] = fma2(a0, w2, acc[0][2]);                               \
            acc[0][3] = fma2(a0, w3, acc[0][3]);                               \
            acc[1][0] = fma2(a1, w0, acc[1][0]);                               \
            acc[1][1] = fma2(a1, w1, acc[1][1]);                               \
            acc[1][2] = fma2(a1, w2, acc[1][2]);                               \
            acc[1][3] = fma2(a1, w3, acc[1][3]);                               \
            acc[2][0] = fma2(a2, w0, acc[2][0]);                               \
            acc[2][1] = fma2(a2, w1, acc[2][1]);                               \
            acc[2][2] = fma2(a2, w2, acc[2][2]);                               \
            acc[2][3] = fma2(a2, w3, acc[2][3]);                               \
            acc[3][0] = fma2(a3, w0, acc[3][0]);                               \
            acc[3][1] = fma2(a3, w1, acc[3][1]);                               \
            acc[3][2] = fma2(a3, w2, acc[3][2]);                               \
            acc[3][3] = fma2(a3, w3, acc[3][3]);                               \
        }

        // x-part (k < 256)
#pragma unroll 4
        for (int k = k0; k < kxe; ++k) KBODY(xbase, k);
        // h-part (k >= 256)
#pragma unroll 4
        for (int k = khs; k < k1; ++k) KBODY(hbase, k);
#undef KBODY

        // ---- dump partials to SMEM (per-thread contiguous slot, 8B aligned) ----
#pragma unroll
        for (int i = 0; i < 4; ++i)
#pragma unroll
            for (int j = 0; j < 4; ++j)
                *(u64*)(slot + (i * 4 + j) * 2) = acc[i][j];

        __syncthreads();

        // ---- reduce 8 k-groups + activations + state update ----
        float g4[4];
        {
            const int lane_base = ((b >> 3) << 2);
            const int elem = (((b >> 1) & 3) * 4 + cl) * 2 + (b & 1);
#pragma unroll
            for (int g = 0; g < 4; ++g) {
                float s = biasr[g];
                int off = (lane_base + g) * RED_STRIDE + elem;
#pragma unroll
                for (int ww = 0; ww < 8; ++ww)
                    s += red[ww * (32 * RED_STRIDE) + off];
                g4[g] = s;
            }
        }

        float ig = sigf(g4[0]);
        float jt = tanhf(g4[1]);
        float fg = sigf(g4[2] + 1.0f);   // forget bias
        float og = sigf(g4[3]);
        float c_new = fg * c_reg + ig * jt;
        float h_new = og * tanhf(c_new);
        if (t < nw_b) { c_reg = c_new; h_reg = h_new; }

        // write own h column slice, transposed [h][b] (coalesced per warp)
        g_hbuf[(t + 1) & 1][(hc0 + cl) * B_SZ + b] = h_reg;
        // next grid_sync (top of loop) provides the fence + __syncthreads
        // guarding red reuse and h visibility
    }

    // ---- final output: [2, B, H] = stack(c, h) ----
    out[(size_t)b * H_DIM + hc0 + cl]                 = c_reg;   // c
    out[(size_t)B_SZ * H_DIM + b * H_DIM + hc0 + cl]  = h_reg;   // h
}

// ============================================================================
extern "C" void kernel_launch(void* const* d_in, const int* in_sizes, int n_in,
                              void* d_out, int out_size) {
    const int*   wi   = (const int*)d_in[0];     // word_indices [B,T]
    const int*   nw   = (const int*)d_in[1];     // num_words   [B]
    const float* emb  = (const float*)d_in[2];   // W_emb       [V,D]
    const float* kern = (const float*)d_in[3];   // kernel      [D+H, 4H]
    const float* bias = (const float*)d_in[4];   // bias        [4H]
    float* out = (float*)d_out;

    cudaFuncSetAttribute(lstm_persistent_kernel,
                         cudaFuncAttributeMaxDynamicSharedMemorySize, SMEM_BYTES);

    gather_transpose_kernel<<<T_LEN, 256>>>(wi, emb);
    lstm_persistent_kernel<<<NCTA, NTHR, SMEM_BYTES>>>(kern, bias, nw, out);
}

// round 11
// speedup vs baseline: 1.0574x; 1.0574x over previous
#include <cuda_runtime.h>
#include <cuda_bf16.h>
#include <math.h>

// Problem constants
#define VOCAB 50000
#define D_EMB 256
#define H_DIM 512
#define B_SZ  64
#define T_LEN 512
#define KTOT  (D_EMB + H_DIM)   // 768
#define G4H   (4 * H_DIM)       // 2048

// Persistent-kernel config
#define NCTA 128                // CTA owns 4 h-cols -> 16 gate cols
#define NTHR 512                // 16 warps = 8 k-groups x 2 batch-halves
#define HC   4
#define XK_PER 32               // x k's per k-group (256/8)
#define HK_PER 64               // h k's per k-group (512/8)

// SMEM: Wd = u64[768][16] duplicated weights (98304B), red = float[16][16][32] (32768B)
#define WD_U64     (KTOT * 16)          // 12288
#define RED_F      (16 * 16 * 32)       // 8192
#define SMEM_BYTES (WD_U64 * 8 + RED_F * 4)   // 131072

typedef unsigned long long u64;

// -------- device scratch --------
__device__ float    g_XT[T_LEN * D_EMB * B_SZ];   // [t][d][b]
__device__ float    g_hbuf[2][H_DIM * B_SZ];      // [h][b] double buffer
__device__ unsigned g_bar_count;
__device__ unsigned g_bar_gen;

__device__ __forceinline__ u64 fma2(u64 a, u64 b, u64 c) {
    u64 d; asm("fma.rn.f32x2 %0, %1, %2, %3;" : "=l"(d) : "l"(a), "l"(b), "l"(c)); return d;
}
__device__ __forceinline__ float sigf(float x) { return 1.0f / (1.0f + __expf(-x)); }

// ============================================================================
// Kernel 1: embedding gather + transpose; zero h0; reset barrier state.
// ============================================================================
__global__ void gather_transpose_kernel(const int* __restrict__ wi,
                                        const float* __restrict__ emb) {
    int t   = blockIdx.x;
    int tid = threadIdx.x;
    int b   = tid & 63;
    int q   = tid >> 6;

    int row = wi[b * T_LEN + t];
    const float* er = emb + (size_t)row * D_EMB + q * 64;
    float* xo = g_XT + (size_t)t * D_EMB * B_SZ;

#pragma unroll
    for (int i = 0; i < 64; i += 4) {
        float4 v = __ldg((const float4*)(er + i));
        int d = q * 64 + i;
        xo[(d + 0) * B_SZ + b] = v.x;
        xo[(d + 1) * B_SZ + b] = v.y;
        xo[(d + 2) * B_SZ + b] = v.z;
        xo[(d + 3) * B_SZ + b] = v.w;
    }
    if (tid < B_SZ) g_hbuf[0][t * B_SZ + tid] = 0.0f;   // block t owns h-row t
    if (t == 0 && tid == 0) { g_bar_gen = 0; g_bar_count = 0; }
}

// ============================================================================
// Kernel 2: persistent LSTM, 128 CTAs x 512 threads.
//  - warp w = (kg = w>>1, bh = w&1): k-octant kg, batch-half bh
//  - lane = (bg = lane>>2, cg = lane&3): 4 batches (bh*32+bg*4..+3), gate cg
//  - acc[2][4]: batch-pair i (0..1) x col cl j (0..3), f32x2 packed
//  - weights duplicated {w,w} in SMEM: 2x LDS.128 = 4 ready operands, 0 MOVs
//  - x-GEMM for step t+1 computed between barrier arrive and wait
// ============================================================================

// per-k inner body: 1 LDG.128 + 2 LDS.128 + 8 FFMA2
#define KBODY(AP, WP)                                               \
    {                                                               \
        ulonglong2 va = __ldcg((const ulonglong2*)(AP));            \
        ulonglong2 wA = *(const ulonglong2*)(WP);                   \
        ulonglong2 wB = *(const ulonglong2*)((WP) + 2);             \
        acc[0][0] = fma2(va.x, wA.x, acc[0][0]);                    \
        acc[0][1] = fma2(va.x, wA.y, acc[0][1]);                    \
        acc[0][2] = fma2(va.x, wB.x, acc[0][2]);                    \
        acc[0][3] = fma2(va.x, wB.y, acc[0][3]);                    \
        acc[1][0] = fma2(va.y, wA.x, acc[1][0]);                    \
        acc[1][1] = fma2(va.y, wA.y, acc[1][1]);                    \
        acc[1][2] = fma2(va.y, wB.x, acc[1][2]);                    \
        acc[1][3] = fma2(va.y, wB.y, acc[1][3]);                    \
    }

__global__ void __launch_bounds__(NTHR, 1)
lstm_persistent_kernel(const float* __restrict__ kern,
                       const float* __restrict__ bias,
                       const int*   __restrict__ num_words,
                       float*       __restrict__ out) {
    extern __shared__ char smem_raw[];
    u64*   Wd  = (u64*)smem_raw;                     // [k][16] duplicated
    float* red = (float*)(smem_raw + WD_U64 * 8);    // [w][e][lane]

    const int tid  = threadIdx.x;
    const int w    = tid >> 5;
    const int lane = tid & 31;
    const int kg   = w >> 1;
    const int bh   = w & 1;
    const int bg   = lane >> 2;
    const int cg   = lane & 3;
    const int hc0  = blockIdx.x * HC;

    // ---- fill duplicated weight slice (once) ----
    for (int idx = tid; idx < WD_U64; idx += NTHR) {
        int k = idx >> 4, c = idx & 15;
        int g = c >> 2, cl = c & 3;
        float v = kern[(size_t)k * G4H + g * H_DIM + hc0 + cl];
        *(float2*)&Wd[idx] = make_float2(v, v);
    }

    // ---- epilogue-role state (tid < 256) ----
    const int b  = tid & 63;
    const int cl = tid >> 6;
    float c_reg = 0.0f, h_reg = 0.0f;
    int nw_b = 0;
    float biasr[4] = {0.f, 0.f, 0.f, 0.f};
    if (tid < 256) {
        nw_b = num_words[b];
#pragma unroll
        for (int g = 0; g < 4; ++g) biasr[g] = bias[g * H_DIM + hc0 + cl];
    }
    __syncthreads();

    const int actoff = bh * 32 + bg * 4;                       // float offset in a k-row
    const u64* wpx0 = Wd + (kg * XK_PER) * 16 + cg * 4;        // x weights base
    const u64* wph0 = Wd + (D_EMB + kg * HK_PER) * 16 + cg * 4;// h weights base

    u64 acc[2][4];

    // ---- prologue: x-part for t = 0 ----
    {
#pragma unroll
        for (int i = 0; i < 2; ++i)
#pragma unroll
            for (int j = 0; j < 4; ++j) acc[i][j] = 0ull;
        const float* ap = g_XT + (kg * XK_PER) * B_SZ + actoff;
        const u64*   wp = wpx0;
#pragma unroll 8
        for (int kk = 0; kk < XK_PER; ++kk) {
            KBODY(ap, wp);
            ap += B_SZ; wp += 16;
        }
    }

    for (int t = 0; t < T_LEN; ++t) {
        if (t > 0) {
            // ---- wait for h(t) (gen reaches t), then accumulate h-part ----
            if (tid == 0) {
                while (*(volatile unsigned*)&g_bar_gen < (unsigned)t) { __nanosleep(32); }
                __threadfence();
            }
            __syncthreads();
            const float* ap = g_hbuf[t & 1] + (kg * HK_PER) * B_SZ + actoff;
            const u64*   wp = wph0;
#pragma unroll 8
            for (int kk = 0; kk < HK_PER; ++kk) {
                KBODY(ap, wp);
                ap += B_SZ; wp += 16;
            }
        }

        // ---- dump partials: red[w][e][lane], conflict-free STS.32 ----
        {
            float* base = red + (w * 16) * 32 + lane;
#pragma unroll
            for (int i = 0; i < 2; ++i)
#pragma unroll
                for (int j = 0; j < 4; ++j) {
                    float2 f = *(float2*)&acc[i][j];
                    int e = (i * 4 + j) * 2;
                    base[e * 32]       = f.x;
                    base[(e + 1) * 32] = f.y;
                }
        }
        __syncthreads();

        // ---- reduce over 8 k-groups + activations + state update ----
        if (tid < 256) {
            const int lane_r = (((b >> 2) & 7) << 2);
            const int e_r    = ((((b >> 1) & 1) * 4 + cl) << 1) | (b & 1);
            const int base_r = (b >> 5) * 512 + e_r * 32 + lane_r;  // bh*16*32 + e*32 + lane
            float g4[4];
#pragma unroll
            for (int g = 0; g < 4; ++g) {
                float s = biasr[g];
                int idx = base_r + g;
#pragma unroll
                for (int kgi = 0; kgi < 8; ++kgi)
                    s += red[idx + kgi * 1024];                     // w stride = 2*16*32
                g4[g] = s;
            }
            float ig = sigf(g4[0]);
            float jt = tanhf(g4[1]);
            float fg = sigf(g4[2] + 1.0f);
            float og = sigf(g4[3]);
            float cn = fg * c_reg + ig * jt;
            float hn = og * tanhf(cn);
            if (t < nw_b) { c_reg = cn; h_reg = hn; }
            g_hbuf[(t + 1) & 1][(hc0 + cl) * B_SZ + b] = h_reg;
        }
        __syncthreads();   // h writes CTA-visible; red reads done before next dump

        // ---- arrive (non-blocking), then overlap x-part of t+1 ----
        if (tid == 0) {
            __threadfence();
            unsigned tkt = atomicAdd(&g_bar_count, 1u);
            if (tkt == NCTA - 1) {
                atomicExch(&g_bar_count, 0u);
                __threadfence();
                atomicAdd(&g_bar_gen, 1u);   // gen = t+1
            }
        }
        if (t + 1 < T_LEN) {
#pragma unroll
            for (int i = 0; i < 2; ++i)
#pragma unroll
                for (int j = 0; j < 4; ++j) acc[i][j] = 0ull;
            const float* ap = g_XT + (size_t)(t + 1) * (D_EMB * B_SZ)
                              + (kg * XK_PER) * B_SZ + actoff;
            const u64*   wp = wpx0;
#pragma unroll 8
            for (int kk = 0; kk < XK_PER; ++kk) {
                KBODY(ap, wp);
                ap += B_SZ; wp += 16;
            }
        }
    }

    // ---- final output [2, B, H] ----
    if (tid < 256) {
        out[(size_t)b * H_DIM + hc0 + cl]                = c_reg;
        out[(size_t)B_SZ * H_DIM + b * H_DIM + hc0 + cl] = h_reg;
    }
}

// ============================================================================
extern "C" void kernel_launch(void* const* d_in, const int* in_sizes, int n_in,
                              void* d_out, int out_size) {
    const int*   wi   = (const int*)d_in[0];
    const int*   nw   = (const int*)d_in[1];
    const float* emb  = (const float*)d_in[2];
    const float* kern = (const float*)d_in[3];
    const float* bias = (const float*)d_in[4];
    float* out = (float*)d_out;

    cudaFuncSetAttribute(lstm_persistent_kernel,
                         cudaFuncAttributeMaxDynamicSharedMemorySize, SMEM_BYTES);

    gather_transpose_kernel<<<T_LEN, 256>>>(wi, emb);
    lstm_persistent_kernel<<<NCTA, NTHR, SMEM_BYTES>>>(kern, bias, nw, out);
}